// round 3
// baseline (speedup 1.0000x reference)
#include <cuda_runtime.h>
#include <math.h>

#define DFIX 4096

// Quarter-row partial dot sums: g_part[row*4 + q] = dot(W[row, q*1024:(q+1)*1024], q-slice)
__device__ float g_part[DFIX * 4];
__device__ float g_gated[8192];   // used by generic fallback path only

// ---------------------------------------------------------------------------
// Kernel A: gate partials. 16384 independent warp tasks, 4 KB stream each.
// Max memory-level parallelism; no cross-warp reduction beyond the warp.
// ---------------------------------------------------------------------------
__global__ __launch_bounds__(256)
void gatep_kernel(const float* __restrict__ q,
                  const float* __restrict__ W) {
    const int gw   = (blockIdx.x * blockDim.x + threadIdx.x) >> 5;
    const int lane = threadIdx.x & 31;
    if (gw >= DFIX * 4) return;
    const int row  = gw >> 2;
    const int quar = gw & 3;

    const float4* w4 = reinterpret_cast<const float4*>(W + (size_t)row * DFIX + quar * 1024);
    const float4* q4 = reinterpret_cast<const float4*>(q + quar * 1024);

    float s = 0.0f;
    #pragma unroll
    for (int i = 0; i < 8; i++) {            // 8*32 = 256 float4 = 1024 floats
        const float4 wv = __ldcs(&w4[lane + i * 32]);   // streamed once
        const float4 qv = q4[lane + i * 32];            // hot in L2
        s += wv.x * qv.x + wv.y * qv.y + wv.z * qv.z + wv.w * qv.w;
    }
    #pragma unroll
    for (int o = 16; o > 0; o >>= 1) s += __shfl_xor_sync(0xFFFFFFFFu, s, o);
    if (lane == 0) g_part[gw] = s;
}

// ---------------------------------------------------------------------------
// Kernel B: persistent sim. Stage gated = sigmoid(sum(partials)+b) into smem
// (folds the partial reduction + activation in for free), then warp-strided
// pattern loop over the whole grid — exactly one wave, no quantization.
// ---------------------------------------------------------------------------
__global__ __launch_bounds__(256, 8)
void simp_kernel(const float* __restrict__ b,
                 const float* __restrict__ mem,
                 float* __restrict__ out,
                 int N, int writeMask) {
    __shared__ float sg[DFIX];

    // Stage: sg[j] = sigmoid(g_part[4j]+g_part[4j+1]+g_part[4j+2]+g_part[4j+3] + b[j])
    const float4* p4 = reinterpret_cast<const float4*>(g_part);
    for (int j = threadIdx.x; j < DFIX; j += blockDim.x) {
        const float4 pv = p4[j];                  // 4 partials of row j, contiguous
        const float x = pv.x + pv.y + pv.z + pv.w + b[j];
        sg[j] = 1.0f / (1.0f + expf(-x));
    }
    __syncthreads();

    const int wid  = threadIdx.x >> 5;
    const int lane = threadIdx.x & 31;
    const int gw     = blockIdx.x * (blockDim.x >> 5) + wid;
    const int gwarps = gridDim.x * (blockDim.x >> 5);
    const float4* sg4 = reinterpret_cast<const float4*>(sg);

    for (int p = gw; p < N; p += gwarps) {
        const float4* m4 = reinterpret_cast<const float4*>(mem + (size_t)p * DFIX);
        float s = 0.0f;
        #pragma unroll 8
        for (int i = 0; i < 32; i++) {            // 32*32 = 1024 float4 = 4096 floats
            const int idx = lane + i * 32;
            const float4 mv = __ldcs(&m4[idx]);   // streamed once, evict-first
            const float4 gv = sg4[idx];
            s += fabsf(mv.x - gv.x) + fabsf(mv.y - gv.y)
               + fabsf(mv.z - gv.z) + fabsf(mv.w - gv.w);
        }
        #pragma unroll
        for (int o = 16; o > 0; o >>= 1) s += __shfl_xor_sync(0xFFFFFFFFu, s, o);
        if (lane == 0) {
            const float sim = 1.0f - s * (1.0f / (float)DFIX);
            out[p] = sim;
            if (writeMask) out[N + p] = (sim >= 0.8f) ? 1.0f : 0.0f;
        }
    }
}

// ---------------------------------------------------------------------------
// Generic-D fallback (round-1 proven version)
// ---------------------------------------------------------------------------
__global__ void gate_kernel(const float* __restrict__ q, const float* __restrict__ W,
                            const float* __restrict__ b, int D) {
    int warp = (blockIdx.x * blockDim.x + threadIdx.x) >> 5;
    int lane = threadIdx.x & 31;
    if (warp >= D) return;
    const float4* w4 = reinterpret_cast<const float4*>(W + (size_t)warp * D);
    const float4* q4 = reinterpret_cast<const float4*>(q);
    int D4 = D >> 2;
    float s = 0.0f;
    for (int i = lane; i < D4; i += 32) {
        float4 wv = w4[i]; float4 qv = q4[i];
        s += wv.x * qv.x + wv.y * qv.y + wv.z * qv.z + wv.w * qv.w;
    }
    for (int o = 16; o > 0; o >>= 1) s += __shfl_xor_sync(0xFFFFFFFFu, s, o);
    if (lane == 0) { float x = s + b[warp]; g_gated[warp] = 1.0f / (1.0f + expf(-x)); }
}

__global__ void sim_kernel(const float* __restrict__ mem, float* __restrict__ out,
                           int N, int D, int writeMask) {
    extern __shared__ float sgd[];
    int D4 = D >> 2;
    const float4* g4 = reinterpret_cast<const float4*>(g_gated);
    float4* sg4 = reinterpret_cast<float4*>(sgd);
    for (int i = threadIdx.x; i < D4; i += blockDim.x) sg4[i] = g4[i];
    __syncthreads();
    int warp = (blockIdx.x * blockDim.x + threadIdx.x) >> 5;
    int lane = threadIdx.x & 31;
    if (warp >= N) return;
    const float4* m4 = reinterpret_cast<const float4*>(mem + (size_t)warp * D);
    float s = 0.0f;
    for (int i = lane; i < D4; i += 32) {
        float4 mv = m4[i]; float4 gv = sg4[i];
        s += fabsf(mv.x - gv.x) + fabsf(mv.y - gv.y)
           + fabsf(mv.z - gv.z) + fabsf(mv.w - gv.w);
    }
    for (int o = 16; o > 0; o >>= 1) s += __shfl_xor_sync(0xFFFFFFFFu, s, o);
    if (lane == 0) {
        float sim = 1.0f - s / (float)D;
        out[warp] = sim;
        if (writeMask) out[N + warp] = (sim >= 0.8f) ? 1.0f : 0.0f;
    }
}

// ---------------------------------------------------------------------------
extern "C" void kernel_launch(void* const* d_in, const int* in_sizes, int n_in,
                              void* d_out, int out_size) {
    const float* q   = (const float*)d_in[0];
    const float* W   = (const float*)d_in[1];
    const float* b   = (const float*)d_in[2];
    const float* mem = (const float*)d_in[3];
    float* out = (float*)d_out;

    int D = in_sizes[0];
    int N = in_sizes[3] / D;
    int writeMask = (out_size >= 2 * N) ? 1 : 0;

    if (D == DFIX) {
        // Kernel A: 16384 warp tasks, 8 warps/block -> 2048 blocks.
        gatep_kernel<<<(DFIX * 4) / 8, 256>>>(q, W);

        // Kernel B: persistent, exactly one wave at 8 blocks/SM.
        int dev = 0, sms = 148;
        cudaGetDevice(&dev);
        cudaDeviceGetAttribute(&sms, cudaDevAttrMultiProcessorCount, dev);
        simp_kernel<<<sms * 8, 256>>>(b, mem, out, N, writeMask);
    } else {
        int blocks1 = (D + 7) / 8;
        gate_kernel<<<blocks1, 256>>>(q, W, b, D);
        int blocks2 = (N + 7) / 8;
        size_t smem = (size_t)D * sizeof(float);
        sim_kernel<<<blocks2, 256, smem>>>(mem, out, N, D, writeMask);
    }
}

// round 4
// speedup vs baseline: 1.0559x; 1.0559x over previous
#include <cuda_runtime.h>
#include <math.h>

#define DFIX 4096

// Quarter-row partial dot sums: g_part[row*4 + q] = dot over 1024-float slice.
__device__ float g_part[DFIX * 4];
__device__ float g_gated[8192];   // generic fallback path only

// ---------------------------------------------------------------------------
// Kernel A: gate partials. 16384 independent warp tasks, 4 KB stream each.
// Plain (caching) loads on W: W is L2-resident across graph replays because
// the sim kernel streams `memory` with .cs (evict-first).
// ---------------------------------------------------------------------------
__global__ __launch_bounds__(256)
void gatep_kernel(const float* __restrict__ q,
                  const float* __restrict__ W) {
    const int gw   = (blockIdx.x * blockDim.x + threadIdx.x) >> 5;
    const int lane = threadIdx.x & 31;
    if (gw >= DFIX * 4) return;
    const int row  = gw >> 2;
    const int quar = gw & 3;

    const float4* w4 = reinterpret_cast<const float4*>(W + (size_t)row * DFIX + quar * 1024);
    const float4* q4 = reinterpret_cast<const float4*>(q + quar * 1024);

    float s = 0.0f;
    #pragma unroll
    for (int i = 0; i < 8; i++) {            // 8*32 = 256 float4 = 1024 floats
        const float4 wv = w4[lane + i * 32];
        const float4 qv = q4[lane + i * 32];
        s += wv.x * qv.x + wv.y * qv.y + wv.z * qv.z + wv.w * qv.w;
    }
    #pragma unroll
    for (int o = 16; o > 0; o >>= 1) s += __shfl_xor_sync(0xFFFFFFFFu, s, o);
    if (lane == 0) g_part[gw] = s;
}

// ---------------------------------------------------------------------------
// Kernel B: sim, round-1 proven schedule (2048 blocks, warp-per-pattern,
// multi-wave self-balancing). Staging folds partial-reduce + bias + sigmoid.
// Memory stream uses .cs (evict-first) to keep W resident in L2 for the
// next replay's gate kernel.
// ---------------------------------------------------------------------------
__global__ __launch_bounds__(256, 8)
void simv_kernel(const float* __restrict__ b,
                 const float* __restrict__ mem,
                 float* __restrict__ out,
                 int N, int writeMask) {
    __shared__ float sg[DFIX];

    // sg[j] = sigmoid(sum of 4 partials of row j + b[j])
    const float4* p4 = reinterpret_cast<const float4*>(g_part);
    for (int j = threadIdx.x; j < DFIX; j += blockDim.x) {
        const float4 pv = p4[j];
        const float x = pv.x + pv.y + pv.z + pv.w + b[j];
        sg[j] = 1.0f / (1.0f + expf(-x));
    }
    __syncthreads();

    const int warp = blockIdx.x * (blockDim.x >> 5) + (threadIdx.x >> 5);
    const int lane = threadIdx.x & 31;
    if (warp >= N) return;

    const float4* m4  = reinterpret_cast<const float4*>(mem + (size_t)warp * DFIX);
    const float4* sg4 = reinterpret_cast<const float4*>(sg);

    float s = 0.0f;
    #pragma unroll 4
    for (int i = lane; i < DFIX / 4; i += 32) {
        const float4 mv = __ldcs(&m4[i]);     // streamed once, evict-first
        const float4 gv = sg4[i];
        s += fabsf(mv.x - gv.x) + fabsf(mv.y - gv.y)
           + fabsf(mv.z - gv.z) + fabsf(mv.w - gv.w);
    }
    #pragma unroll
    for (int o = 16; o > 0; o >>= 1) s += __shfl_xor_sync(0xFFFFFFFFu, s, o);

    if (lane == 0) {
        const float sim = 1.0f - s * (1.0f / (float)DFIX);
        out[warp] = sim;
        if (writeMask) out[N + warp] = (sim >= 0.8f) ? 1.0f : 0.0f;
    }
}

// ---------------------------------------------------------------------------
// Generic-D fallback (round-1 proven version)
// ---------------------------------------------------------------------------
__global__ void gate_kernel(const float* __restrict__ q, const float* __restrict__ W,
                            const float* __restrict__ b, int D) {
    int warp = (blockIdx.x * blockDim.x + threadIdx.x) >> 5;
    int lane = threadIdx.x & 31;
    if (warp >= D) return;
    const float4* w4 = reinterpret_cast<const float4*>(W + (size_t)warp * D);
    const float4* q4 = reinterpret_cast<const float4*>(q);
    int D4 = D >> 2;
    float s = 0.0f;
    for (int i = lane; i < D4; i += 32) {
        float4 wv = w4[i]; float4 qv = q4[i];
        s += wv.x * qv.x + wv.y * qv.y + wv.z * qv.z + wv.w * qv.w;
    }
    for (int o = 16; o > 0; o >>= 1) s += __shfl_xor_sync(0xFFFFFFFFu, s, o);
    if (lane == 0) { float x = s + b[warp]; g_gated[warp] = 1.0f / (1.0f + expf(-x)); }
}

__global__ void sim_kernel(const float* __restrict__ mem, float* __restrict__ out,
                           int N, int D, int writeMask) {
    extern __shared__ float sgd[];
    int D4 = D >> 2;
    const float4* g4 = reinterpret_cast<const float4*>(g_gated);
    float4* sg4 = reinterpret_cast<float4*>(sgd);
    for (int i = threadIdx.x; i < D4; i += blockDim.x) sg4[i] = g4[i];
    __syncthreads();
    int warp = (blockIdx.x * blockDim.x + threadIdx.x) >> 5;
    int lane = threadIdx.x & 31;
    if (warp >= N) return;
    const float4* m4 = reinterpret_cast<const float4*>(mem + (size_t)warp * D);
    float s = 0.0f;
    for (int i = lane; i < D4; i += 32) {
        float4 mv = m4[i]; float4 gv = sg4[i];
        s += fabsf(mv.x - gv.x) + fabsf(mv.y - gv.y)
           + fabsf(mv.z - gv.z) + fabsf(mv.w - gv.w);
    }
    for (int o = 16; o > 0; o >>= 1) s += __shfl_xor_sync(0xFFFFFFFFu, s, o);
    if (lane == 0) {
        float sim = 1.0f - s / (float)D;
        out[warp] = sim;
        if (writeMask) out[N + warp] = (sim >= 0.8f) ? 1.0f : 0.0f;
    }
}

// ---------------------------------------------------------------------------
extern "C" void kernel_launch(void* const* d_in, const int* in_sizes, int n_in,
                              void* d_out, int out_size) {
    const float* q   = (const float*)d_in[0];
    const float* W   = (const float*)d_in[1];
    const float* b   = (const float*)d_in[2];
    const float* mem = (const float*)d_in[3];
    float* out = (float*)d_out;

    int D = in_sizes[0];
    int N = in_sizes[3] / D;
    int writeMask = (out_size >= 2 * N) ? 1 : 0;

    if (D == DFIX) {
        // Kernel A: 16384 warp tasks, 8 warps/block -> 2048 blocks.
        gatep_kernel<<<(DFIX * 4) / 8, 256>>>(q, W);
        // Kernel B: warp-per-pattern, N/8 blocks (multi-wave, self-balancing).
        simv_kernel<<<(N + 7) / 8, 256>>>(b, mem, out, N, writeMask);
    } else {
        int blocks1 = (D + 7) / 8;
        gate_kernel<<<blocks1, 256>>>(q, W, b, D);
        int blocks2 = (N + 7) / 8;
        size_t smem = (size_t)D * sizeof(float);
        sim_kernel<<<blocks2, 256, smem>>>(mem, out, N, D, writeMask);
    }
}

// round 5
// speedup vs baseline: 1.0684x; 1.0118x over previous
#include <cuda_runtime.h>
#include <math.h>

#define DFIX 4096

__device__ float g_gated[8192];

// ---------------------------------------------------------------------------
// Gate: one block per output row. 8 warps split the 4096-float dot, smem
// block-reduce, thread 0 adds bias + sigmoid -> g_gated[row].
// 4096 independent blocks => high MLP, DRAM-bound floor ~10us for 64MB.
// ---------------------------------------------------------------------------
__global__ __launch_bounds__(256)
void gatep2_kernel(const float* __restrict__ q,
                   const float* __restrict__ W,
                   const float* __restrict__ b) {
    __shared__ float red[8];
    const int row  = blockIdx.x;
    const int wid  = threadIdx.x >> 5;
    const int lane = threadIdx.x & 31;

    const float4* w4 = reinterpret_cast<const float4*>(W + (size_t)row * DFIX);
    const float4* q4 = reinterpret_cast<const float4*>(q);

    float s = 0.0f;
    const int base = wid * 128;            // 128 float4 per warp
    #pragma unroll
    for (int i = 0; i < 4; i++) {
        const int idx = base + lane + i * 32;
        const float4 wv = w4[idx];
        const float4 qv = q4[idx];
        s += wv.x * qv.x + wv.y * qv.y + wv.z * qv.z + wv.w * qv.w;
    }
    #pragma unroll
    for (int o = 16; o > 0; o >>= 1) s += __shfl_xor_sync(0xFFFFFFFFu, s, o);
    if (lane == 0) red[wid] = s;
    __syncthreads();
    if (threadIdx.x == 0) {
        const float tot = red[0] + red[1] + red[2] + red[3]
                        + red[4] + red[5] + red[6] + red[7];
        const float x = tot + b[row];
        g_gated[row] = 1.0f / (1.0f + expf(-x));
    }
}

// ---------------------------------------------------------------------------
// Sim: exact round-1 proven configuration (44.9us @ 76.8% DRAM).
// Warp-per-pattern, 16KB pure-copy smem staging, plain caching loads,
// unroll 4, 2048 blocks (multi-wave self-balancing).
// ---------------------------------------------------------------------------
__global__ __launch_bounds__(256, 8)
void sim1_kernel(const float* __restrict__ mem,
                 float* __restrict__ out,
                 int N, int writeMask) {
    __shared__ float sg[DFIX];

    const float4* g4  = reinterpret_cast<const float4*>(g_gated);
    float4*       sg4 = reinterpret_cast<float4*>(sg);
    for (int i = threadIdx.x; i < DFIX / 4; i += blockDim.x) sg4[i] = g4[i];
    __syncthreads();

    const int warp = blockIdx.x * (blockDim.x >> 5) + (threadIdx.x >> 5);
    const int lane = threadIdx.x & 31;
    if (warp >= N) return;

    const float4* m4 = reinterpret_cast<const float4*>(mem + (size_t)warp * DFIX);

    float s = 0.0f;
    #pragma unroll 4
    for (int i = lane; i < DFIX / 4; i += 32) {
        const float4 mv = m4[i];
        const float4 gv = sg4[i];
        s += fabsf(mv.x - gv.x) + fabsf(mv.y - gv.y)
           + fabsf(mv.z - gv.z) + fabsf(mv.w - gv.w);
    }
    #pragma unroll
    for (int o = 16; o > 0; o >>= 1) s += __shfl_xor_sync(0xFFFFFFFFu, s, o);

    if (lane == 0) {
        const float sim = 1.0f - s * (1.0f / (float)DFIX);
        out[warp] = sim;
        if (writeMask) out[N + warp] = (sim >= 0.8f) ? 1.0f : 0.0f;
    }
}

// ---------------------------------------------------------------------------
// Generic-D fallback (round-1 proven version)
// ---------------------------------------------------------------------------
__global__ void gate_kernel(const float* __restrict__ q, const float* __restrict__ W,
                            const float* __restrict__ b, int D) {
    int warp = (blockIdx.x * blockDim.x + threadIdx.x) >> 5;
    int lane = threadIdx.x & 31;
    if (warp >= D) return;
    const float4* w4 = reinterpret_cast<const float4*>(W + (size_t)warp * D);
    const float4* q4 = reinterpret_cast<const float4*>(q);
    int D4 = D >> 2;
    float s = 0.0f;
    for (int i = lane; i < D4; i += 32) {
        float4 wv = w4[i]; float4 qv = q4[i];
        s += wv.x * qv.x + wv.y * qv.y + wv.z * qv.z + wv.w * qv.w;
    }
    for (int o = 16; o > 0; o >>= 1) s += __shfl_xor_sync(0xFFFFFFFFu, s, o);
    if (lane == 0) { float x = s + b[warp]; g_gated[warp] = 1.0f / (1.0f + expf(-x)); }
}

__global__ void sim_kernel(const float* __restrict__ mem, float* __restrict__ out,
                           int N, int D, int writeMask) {
    extern __shared__ float sgd[];
    int D4 = D >> 2;
    const float4* g4 = reinterpret_cast<const float4*>(g_gated);
    float4* sg4 = reinterpret_cast<float4*>(sgd);
    for (int i = threadIdx.x; i < D4; i += blockDim.x) sg4[i] = g4[i];
    __syncthreads();
    int warp = (blockIdx.x * blockDim.x + threadIdx.x) >> 5;
    int lane = threadIdx.x & 31;
    if (warp >= N) return;
    const float4* m4 = reinterpret_cast<const float4*>(mem + (size_t)warp * D);
    float s = 0.0f;
    for (int i = lane; i < D4; i += 32) {
        float4 mv = m4[i]; float4 gv = sg4[i];
        s += fabsf(mv.x - gv.x) + fabsf(mv.y - gv.y)
           + fabsf(mv.z - gv.z) + fabsf(mv.w - gv.w);
    }
    for (int o = 16; o > 0; o >>= 1) s += __shfl_xor_sync(0xFFFFFFFFu, s, o);
    if (lane == 0) {
        float sim = 1.0f - s / (float)D;
        out[warp] = sim;
        if (writeMask) out[N + warp] = (sim >= 0.8f) ? 1.0f : 0.0f;
    }
}

// ---------------------------------------------------------------------------
extern "C" void kernel_launch(void* const* d_in, const int* in_sizes, int n_in,
                              void* d_out, int out_size) {
    const float* q   = (const float*)d_in[0];
    const float* W   = (const float*)d_in[1];
    const float* b   = (const float*)d_in[2];
    const float* mem = (const float*)d_in[3];
    float* out = (float*)d_out;

    int D = in_sizes[0];
    int N = in_sizes[3] / D;
    int writeMask = (out_size >= 2 * N) ? 1 : 0;

    if (D == DFIX) {
        gatep2_kernel<<<DFIX, 256>>>(q, W, b);              // block per row
        sim1_kernel<<<(N + 7) / 8, 256>>>(mem, out, N, writeMask);
    } else {
        int blocks1 = (D + 7) / 8;
        gate_kernel<<<blocks1, 256>>>(q, W, b, D);
        int blocks2 = (N + 7) / 8;
        size_t smem = (size_t)D * sizeof(float);
        sim_kernel<<<blocks2, 256, smem>>>(mem, out, N, D, writeMask);
    }
}

// round 6
// speedup vs baseline: 1.2156x; 1.1378x over previous
#include <cuda_runtime.h>
#include <math.h>

#define DFIX 4096

__device__ float g_gated[8192];

// ---------------------------------------------------------------------------
// Gate: one block per output row. 8 warps split the 4096-float dot, smem
// block-reduce, thread 0 adds bias + sigmoid -> g_gated[row].
// Plain caching loads on W: with the sim kernel streaming `memory` via .cs
// (evict-first), W (64MB) stays resident in L2 (126MB) across graph replays
// => gate runs at L2 bandwidth (~11 TB/s, measured 5.7us in round 3).
// ---------------------------------------------------------------------------
__global__ __launch_bounds__(256)
void gatep2_kernel(const float* __restrict__ q,
                   const float* __restrict__ W,
                   const float* __restrict__ b) {
    __shared__ float red[8];
    const int row  = blockIdx.x;
    const int wid  = threadIdx.x >> 5;
    const int lane = threadIdx.x & 31;

    const float4* w4 = reinterpret_cast<const float4*>(W + (size_t)row * DFIX);
    const float4* q4 = reinterpret_cast<const float4*>(q);

    float s = 0.0f;
    const int base = wid * 128;            // 128 float4 per warp
    #pragma unroll
    for (int i = 0; i < 4; i++) {
        const int idx = base + lane + i * 32;
        const float4 wv = w4[idx];
        const float4 qv = q4[idx];
        s += wv.x * qv.x + wv.y * qv.y + wv.z * qv.z + wv.w * qv.w;
    }
    #pragma unroll
    for (int o = 16; o > 0; o >>= 1) s += __shfl_xor_sync(0xFFFFFFFFu, s, o);
    if (lane == 0) red[wid] = s;
    __syncthreads();
    if (threadIdx.x == 0) {
        const float tot = red[0] + red[1] + red[2] + red[3]
                        + red[4] + red[5] + red[6] + red[7];
        const float x = tot + b[row];
        g_gated[row] = 1.0f / (1.0f + expf(-x));
    }
}

// ---------------------------------------------------------------------------
// Sim: round-1/round-5 proven configuration (warp-per-pattern, 16KB pure-copy
// smem staging, unroll 4, 2048 blocks) with ONE change: .cs (evict-first)
// loads on the 256MB memory stream, protecting W's L2 residency for the
// next replay's gate kernel.
// ---------------------------------------------------------------------------
__global__ __launch_bounds__(256, 8)
void sim1_kernel(const float* __restrict__ mem,
                 float* __restrict__ out,
                 int N, int writeMask) {
    __shared__ float sg[DFIX];

    const float4* g4  = reinterpret_cast<const float4*>(g_gated);
    float4*       sg4 = reinterpret_cast<float4*>(sg);
    for (int i = threadIdx.x; i < DFIX / 4; i += blockDim.x) sg4[i] = g4[i];
    __syncthreads();

    const int warp = blockIdx.x * (blockDim.x >> 5) + (threadIdx.x >> 5);
    const int lane = threadIdx.x & 31;
    if (warp >= N) return;

    const float4* m4 = reinterpret_cast<const float4*>(mem + (size_t)warp * DFIX);

    float s = 0.0f;
    #pragma unroll 4
    for (int i = lane; i < DFIX / 4; i += 32) {
        const float4 mv = __ldcs(&m4[i]);   // evict-first: don't pollute L2
        const float4 gv = sg4[i];
        s += fabsf(mv.x - gv.x) + fabsf(mv.y - gv.y)
           + fabsf(mv.z - gv.z) + fabsf(mv.w - gv.w);
    }
    #pragma unroll
    for (int o = 16; o > 0; o >>= 1) s += __shfl_xor_sync(0xFFFFFFFFu, s, o);

    if (lane == 0) {
        const float sim = 1.0f - s * (1.0f / (float)DFIX);
        out[warp] = sim;
        if (writeMask) out[N + warp] = (sim >= 0.8f) ? 1.0f : 0.0f;
    }
}

// ---------------------------------------------------------------------------
// Generic-D fallback (round-1 proven version)
// ---------------------------------------------------------------------------
__global__ void gate_kernel(const float* __restrict__ q, const float* __restrict__ W,
                            const float* __restrict__ b, int D) {
    int warp = (blockIdx.x * blockDim.x + threadIdx.x) >> 5;
    int lane = threadIdx.x & 31;
    if (warp >= D) return;
    const float4* w4 = reinterpret_cast<const float4*>(W + (size_t)warp * D);
    const float4* q4 = reinterpret_cast<const float4*>(q);
    int D4 = D >> 2;
    float s = 0.0f;
    for (int i = lane; i < D4; i += 32) {
        float4 wv = w4[i]; float4 qv = q4[i];
        s += wv.x * qv.x + wv.y * qv.y + wv.z * qv.z + wv.w * qv.w;
    }
    for (int o = 16; o > 0; o >>= 1) s += __shfl_xor_sync(0xFFFFFFFFu, s, o);
    if (lane == 0) { float x = s + b[warp]; g_gated[warp] = 1.0f / (1.0f + expf(-x)); }
}

__global__ void sim_kernel(const float* __restrict__ mem, float* __restrict__ out,
                           int N, int D, int writeMask) {
    extern __shared__ float sgd[];
    int D4 = D >> 2;
    const float4* g4 = reinterpret_cast<const float4*>(g_gated);
    float4* sg4 = reinterpret_cast<float4*>(sgd);
    for (int i = threadIdx.x; i < D4; i += blockDim.x) sg4[i] = g4[i];
    __syncthreads();
    int warp = (blockIdx.x * blockDim.x + threadIdx.x) >> 5;
    int lane = threadIdx.x & 31;
    if (warp >= N) return;
    const float4* m4 = reinterpret_cast<const float4*>(mem + (size_t)warp * D);
    float s = 0.0f;
    for (int i = lane; i < D4; i += 32) {
        float4 mv = m4[i]; float4 gv = sg4[i];
        s += fabsf(mv.x - gv.x) + fabsf(mv.y - gv.y)
           + fabsf(mv.z - gv.z) + fabsf(mv.w - gv.w);
    }
    for (int o = 16; o > 0; o >>= 1) s += __shfl_xor_sync(0xFFFFFFFFu, s, o);
    if (lane == 0) {
        float sim = 1.0f - s / (float)D;
        out[warp] = sim;
        if (writeMask) out[N + warp] = (sim >= 0.8f) ? 1.0f : 0.0f;
    }
}

// ---------------------------------------------------------------------------
extern "C" void kernel_launch(void* const* d_in, const int* in_sizes, int n_in,
                              void* d_out, int out_size) {
    const float* q   = (const float*)d_in[0];
    const float* W   = (const float*)d_in[1];
    const float* b   = (const float*)d_in[2];
    const float* mem = (const float*)d_in[3];
    float* out = (float*)d_out;

    int D = in_sizes[0];
    int N = in_sizes[3] / D;
    int writeMask = (out_size >= 2 * N) ? 1 : 0;

    if (D == DFIX) {
        gatep2_kernel<<<DFIX, 256>>>(q, W, b);                 // block per row
        sim1_kernel<<<(N + 7) / 8, 256>>>(mem, out, N, writeMask);
    } else {
        int blocks1 = (D + 7) / 8;
        gate_kernel<<<blocks1, 256>>>(q, W, b, D);
        int blocks2 = (N + 7) / 8;
        size_t smem = (size_t)D * sizeof(float);
        sim_kernel<<<blocks2, 256, smem>>>(mem, out, N, D, writeMask);
    }
}

// round 7
// speedup vs baseline: 1.2733x; 1.0475x over previous
#include <cuda_runtime.h>
#include <math.h>

#define DFIX 4096

__device__ float g_gated[8192];

// ---------------------------------------------------------------------------
// Gate: one block per output row (proven R5/R6 config). W is L2-resident
// across graph replays because sim streams `memory` with .cs.
// ---------------------------------------------------------------------------
__global__ __launch_bounds__(256)
void gatep2_kernel(const float* __restrict__ q,
                   const float* __restrict__ W,
                   const float* __restrict__ b) {
    __shared__ float red[8];
    const int row  = blockIdx.x;
    const int wid  = threadIdx.x >> 5;
    const int lane = threadIdx.x & 31;

    const float4* w4 = reinterpret_cast<const float4*>(W + (size_t)row * DFIX);
    const float4* q4 = reinterpret_cast<const float4*>(q);

    float s = 0.0f;
    const int base = wid * 128;
    #pragma unroll
    for (int i = 0; i < 4; i++) {
        const int idx = base + lane + i * 32;
        const float4 wv = w4[idx];
        const float4 qv = q4[idx];
        s += wv.x * qv.x + wv.y * qv.y + wv.z * qv.z + wv.w * qv.w;
    }
    #pragma unroll
    for (int o = 16; o > 0; o >>= 1) s += __shfl_xor_sync(0xFFFFFFFFu, s, o);
    if (lane == 0) red[wid] = s;
    __syncthreads();
    if (threadIdx.x == 0) {
        const float tot = red[0] + red[1] + red[2] + red[3]
                        + red[4] + red[5] + red[6] + red[7];
        const float x = tot + b[row];
        g_gated[row] = 1.0f / (1.0f + expf(-x));
    }
}

// ---------------------------------------------------------------------------
// Sim v2: BLOCK-per-pattern (fine-grained: 13.8 tasks per resident slot,
// tail loss ~2% vs 13.5% for warp-per-pattern).
// No smem staging: gated is read via __ldg and stays L1-resident per SM
// (16KB, identical access pattern across blocks; the .cs memory stream is
// evict-first and leaves it alone). Each thread: 4 float4 from memory +
// 4 float4 from gated, fully unrolled, then block reduce.
// ---------------------------------------------------------------------------
__global__ __launch_bounds__(256, 8)
void sim2_kernel(const float* __restrict__ mem,
                 const float* __restrict__ gated,
                 float* __restrict__ out,
                 int N, int writeMask) {
    __shared__ float red[8];
    const int p    = blockIdx.x;
    const int tid  = threadIdx.x;
    const int wid  = tid >> 5;
    const int lane = tid & 31;

    const float4* m4 = reinterpret_cast<const float4*>(mem + (size_t)p * DFIX);
    const float4* g4 = reinterpret_cast<const float4*>(gated);

    // 1024 float4 / 256 threads = 4 per thread, stride 256 (coalesced).
    float s = 0.0f;
    #pragma unroll
    for (int i = 0; i < 4; i++) {
        const int idx = tid + i * 256;
        const float4 mv = __ldcs(&m4[idx]);   // stream once, evict-first
        const float4 gv = __ldg(&g4[idx]);    // L1-resident working set
        s += fabsf(mv.x - gv.x) + fabsf(mv.y - gv.y)
           + fabsf(mv.z - gv.z) + fabsf(mv.w - gv.w);
    }
    #pragma unroll
    for (int o = 16; o > 0; o >>= 1) s += __shfl_xor_sync(0xFFFFFFFFu, s, o);
    if (lane == 0) red[wid] = s;
    __syncthreads();
    if (tid == 0) {
        const float tot = red[0] + red[1] + red[2] + red[3]
                        + red[4] + red[5] + red[6] + red[7];
        const float sim = 1.0f - tot * (1.0f / (float)DFIX);
        out[p] = sim;
        if (writeMask) out[N + p] = (sim >= 0.8f) ? 1.0f : 0.0f;
    }
}

// ---------------------------------------------------------------------------
// Generic-D fallback (round-1 proven version)
// ---------------------------------------------------------------------------
__global__ void gate_kernel(const float* __restrict__ q, const float* __restrict__ W,
                            const float* __restrict__ b, int D) {
    int warp = (blockIdx.x * blockDim.x + threadIdx.x) >> 5;
    int lane = threadIdx.x & 31;
    if (warp >= D) return;
    const float4* w4 = reinterpret_cast<const float4*>(W + (size_t)warp * D);
    const float4* q4 = reinterpret_cast<const float4*>(q);
    int D4 = D >> 2;
    float s = 0.0f;
    for (int i = lane; i < D4; i += 32) {
        float4 wv = w4[i]; float4 qv = q4[i];
        s += wv.x * qv.x + wv.y * qv.y + wv.z * qv.z + wv.w * qv.w;
    }
    for (int o = 16; o > 0; o >>= 1) s += __shfl_xor_sync(0xFFFFFFFFu, s, o);
    if (lane == 0) { float x = s + b[warp]; g_gated[warp] = 1.0f / (1.0f + expf(-x)); }
}

__global__ void sim_kernel(const float* __restrict__ mem, float* __restrict__ out,
                           int N, int D, int writeMask) {
    extern __shared__ float sgd[];
    int D4 = D >> 2;
    const float4* g4 = reinterpret_cast<const float4*>(g_gated);
    float4* sg4 = reinterpret_cast<float4*>(sgd);
    for (int i = threadIdx.x; i < D4; i += blockDim.x) sg4[i] = g4[i];
    __syncthreads();
    int warp = (blockIdx.x * blockDim.x + threadIdx.x) >> 5;
    int lane = threadIdx.x & 31;
    if (warp >= N) return;
    const float4* m4 = reinterpret_cast<const float4*>(mem + (size_t)warp * D);
    float s = 0.0f;
    for (int i = lane; i < D4; i += 32) {
        float4 mv = m4[i]; float4 gv = sg4[i];
        s += fabsf(mv.x - gv.x) + fabsf(mv.y - gv.y)
           + fabsf(mv.z - gv.z) + fabsf(mv.w - gv.w);
    }
    for (int o = 16; o > 0; o >>= 1) s += __shfl_xor_sync(0xFFFFFFFFu, s, o);
    if (lane == 0) {
        float sim = 1.0f - s / (float)D;
        out[warp] = sim;
        if (writeMask) out[N + warp] = (sim >= 0.8f) ? 1.0f : 0.0f;
    }
}

// ---------------------------------------------------------------------------
extern "C" void kernel_launch(void* const* d_in, const int* in_sizes, int n_in,
                              void* d_out, int out_size) {
    const float* q   = (const float*)d_in[0];
    const float* W   = (const float*)d_in[1];
    const float* b   = (const float*)d_in[2];
    const float* mem = (const float*)d_in[3];
    float* out = (float*)d_out;

    int D = in_sizes[0];
    int N = in_sizes[3] / D;
    int writeMask = (out_size >= 2 * N) ? 1 : 0;

    if (D == DFIX) {
        gatep2_kernel<<<DFIX, 256>>>(q, W, b);      // block per row
        // Block-per-pattern: N blocks, fine-grained scheduling.
        const float* gated_ptr = nullptr;
        cudaGetSymbolAddress((void**)&gated_ptr, g_gated);
        sim2_kernel<<<N, 256>>>(mem, gated_ptr, out, N, writeMask);
    } else {
        int blocks1 = (D + 7) / 8;
        gate_kernel<<<blocks1, 256>>>(q, W, b, D);
        int blocks2 = (N + 7) / 8;
        size_t smem = (size_t)D * sizeof(float);
        sim_kernel<<<blocks2, 256, smem>>>(mem, out, N, D, writeMask);
    }
}